// round 5
// baseline (speedup 1.0000x reference)
#include <cuda_runtime.h>
#include <math.h>

#define SEQ 2048
#define HID 2048
#define NH  16
#define NKV 8
#define HD  128

// Scratch (allocation-free: __device__ globals)
__device__ float g_q[(size_t)SEQ * NH * HD];        // [S, 2048]
__device__ float g_k[(size_t)SEQ * NKV * HD];       // [S, 1024]
__device__ float g_v[(size_t)SEQ * NKV * HD];       // [S, 1024]
__device__ float g_scores[(size_t)NH * SEQ * SEQ];  // 256 MB
__device__ float g_ctx[(size_t)SEQ * NH * HD];      // [S, 2048]

// ---------------------------------------------------------------------------
// Generic batched tiled SGEMM.
//   NT (TB_NT=true):  C[m,n] = sum_k A[m,k] * B[n,k]
//   NN (TB_NT=false): C[m,n] = sum_k A[m,k] * B[k,n]
// Per-batch offsets: A += bz*sA, B += (bz/bdiv)*sB, C += bz*sC.
// causalSkip: skip tiles fully above the diagonal (score GEMM).
// causalKlim: clamp K-loop to m0+BM (context GEMM; masked P entries are 0).
// All dims must be multiples of the tile sizes (true for this problem).
// ---------------------------------------------------------------------------
template <bool TB_NT>
__global__ __launch_bounds__(256)
void sgemm(const float* __restrict__ A, const float* __restrict__ B,
           float* __restrict__ C,
           int M, int N, int K, int lda, int ldb, int ldc,
           long long sA, long long sB, long long sC, int bdiv,
           int causalSkip, int causalKlim)
{
    constexpr int BM = 128, BN = 128, BK = 8, TM = 8, TN = 8;
    const int bz = blockIdx.z;
    A += (long long)bz * sA;
    B += (long long)(bz / bdiv) * sB;
    C += (long long)bz * sC;

    const int m0 = blockIdx.y * BM;
    const int n0 = blockIdx.x * BN;
    if (causalSkip && n0 > m0 + BM - 1) return;   // fully masked tile
    int Keff = K;
    if (causalKlim) Keff = min(K, m0 + BM);       // multiple of BK (m0 % 128 == 0)

    __shared__ float As[BK][BM];
    __shared__ float Bs[BK][BN];

    const int tid  = threadIdx.x;
    const int arow = tid >> 1;            // 0..127
    const int acol = (tid & 1) * 4;       // 0 or 4
    const int tx   = tid & 15;            // 0..15
    const int ty   = tid >> 4;            // 0..15

    float acc[TM][TN] = {};

    for (int k0 = 0; k0 < Keff; k0 += BK) {
        // A tile: [BM rows, BK cols], stored transposed into As[k][m]
        const float4 a4 = *(const float4*)(A + (long long)(m0 + arow) * lda + k0 + acol);
        As[acol + 0][arow] = a4.x;
        As[acol + 1][arow] = a4.y;
        As[acol + 2][arow] = a4.z;
        As[acol + 3][arow] = a4.w;

        if (TB_NT) {
            // B tile: rows n0..n0+127, cols k0..k0+7  -> Bs[k][n]
            const float4 b4 = *(const float4*)(B + (long long)(n0 + arow) * ldb + k0 + acol);
            Bs[acol + 0][arow] = b4.x;
            Bs[acol + 1][arow] = b4.y;
            Bs[acol + 2][arow] = b4.z;
            Bs[acol + 3][arow] = b4.w;
        } else {
            // B tile: rows k0..k0+7, cols n0..n0+127 -> Bs[k][n] (coalesced)
            const int brow = tid >> 5;          // 0..7
            const int bcol = (tid & 31) * 4;    // 0..124
            const float4 b4 = *(const float4*)(B + (long long)(k0 + brow) * ldb + n0 + bcol);
            *(float4*)&Bs[brow][bcol] = b4;
        }
        __syncthreads();

        #pragma unroll
        for (int kk = 0; kk < BK; kk++) {
            float ra[TM], rb[TN];
            #pragma unroll
            for (int i = 0; i < TM; i++) ra[i] = As[kk][ty * TM + i];
            #pragma unroll
            for (int j = 0; j < TN; j++) rb[j] = Bs[kk][tx * TN + j];
            #pragma unroll
            for (int i = 0; i < TM; i++)
                #pragma unroll
                for (int j = 0; j < TN; j++)
                    acc[i][j] = fmaf(ra[i], rb[j], acc[i][j]);
        }
        __syncthreads();
    }

    #pragma unroll
    for (int i = 0; i < TM; i++) {
        float* crow = C + (long long)(m0 + ty * TM + i) * ldc + n0 + tx * TN;
        #pragma unroll
        for (int j = 0; j < TN; j += 4) {
            float4 v4 = make_float4(acc[i][j], acc[i][j + 1], acc[i][j + 2], acc[i][j + 3]);
            *(float4*)(crow + j) = v4;
        }
    }
}

// ---------------------------------------------------------------------------
// RoPE (rotate-half, non-interleaved), in-place on [S, heads, 128]
// ---------------------------------------------------------------------------
__global__ void rope_kernel(float* __restrict__ t,
                            const float* __restrict__ cosT,
                            const float* __restrict__ sinT, int heads)
{
    const int idx = blockIdx.x * blockDim.x + threadIdx.x;
    const int total = SEQ * heads * (HD / 2);
    if (idx >= total) return;
    const int d = idx % (HD / 2);
    const int h = (idx / (HD / 2)) % heads;
    const int s = idx / ((HD / 2) * heads);

    const float c1 = cosT[s * HD + d];
    const float s1 = sinT[s * HD + d];
    const float c2 = cosT[s * HD + d + HD / 2];
    const float s2 = sinT[s * HD + d + HD / 2];

    float* row = t + (long long)s * heads * HD + h * HD;
    const float x1 = row[d];
    const float x2 = row[d + HD / 2];
    row[d]          = x1 * c1 - x2 * s1;
    row[d + HD / 2] = x2 * c2 + x1 * s2;
}

// ---------------------------------------------------------------------------
// Causal softmax over one (head, query) row; zero-fills the masked tail so
// the context GEMM's clamped K-loop is exact.
// ---------------------------------------------------------------------------
__global__ __launch_bounds__(256)
void softmax_kernel(float* __restrict__ scores)
{
    const int q = blockIdx.x;
    const int h = blockIdx.y;
    float* row = scores + ((size_t)h * SEQ + q) * SEQ;
    const int tid = threadIdx.x;
    const float scale = 0.08838834764831845f;  // 1/sqrt(128)
    const int n = q + 1;

    __shared__ float red[256];

    float mx = -INFINITY;
    for (int k = tid; k < n; k += 256) mx = fmaxf(mx, row[k] * scale);
    red[tid] = mx;
    __syncthreads();
    for (int st = 128; st > 0; st >>= 1) {
        if (tid < st) red[tid] = fmaxf(red[tid], red[tid + st]);
        __syncthreads();
    }
    mx = red[0];
    __syncthreads();

    float sum = 0.0f;
    for (int k = tid; k < n; k += 256) {
        const float e = __expf(row[k] * scale - mx);
        row[k] = e;
        sum += e;
    }
    red[tid] = sum;
    __syncthreads();
    for (int st = 128; st > 0; st >>= 1) {
        if (tid < st) red[tid] += red[tid + st];
        __syncthreads();
    }
    const float inv = 1.0f / red[0];
    __syncthreads();

    for (int k = tid; k < n; k += 256) row[k] *= inv;
    for (int k = n + tid; k < SEQ; k += 256) row[k] = 0.0f;
}

// ---------------------------------------------------------------------------
extern "C" void kernel_launch(void* const* d_in, const int* in_sizes, int n_in,
                              void* d_out, int out_size)
{
    const float* x    = (const float*)d_in[0];  // [1, 2048, 2048]
    const float* Wq   = (const float*)d_in[1];  // [2048, 2048]
    const float* Wk   = (const float*)d_in[2];  // [1024, 2048]
    const float* Wv   = (const float*)d_in[3];  // [1024, 2048]
    const float* Wo   = (const float*)d_in[4];  // [2048, 2048]
    const float* cosT = (const float*)d_in[5];  // [2048, 128]
    const float* sinT = (const float*)d_in[6];  // [2048, 128]
    float* out = (float*)d_out;

    float* q   = g_q;
    float* k   = g_k;
    float* v   = g_v;
    float* sc  = g_scores;
    float* ctx = g_ctx;
    // device-symbol addresses are valid directly in kernel args (same module)

    const dim3 blk(256);

    // QKV projections (NT)
    sgemm<true><<<dim3(16, 16, 1), blk>>>(x, Wq, q, SEQ, 2048, HID,
                                          HID, HID, 2048, 0, 0, 0, 1, 0, 0);
    sgemm<true><<<dim3(8, 16, 1), blk>>>(x, Wk, k, SEQ, 1024, HID,
                                         HID, HID, 1024, 0, 0, 0, 1, 0, 0);
    sgemm<true><<<dim3(8, 16, 1), blk>>>(x, Wv, v, SEQ, 1024, HID,
                                         HID, HID, 1024, 0, 0, 0, 1, 0, 0);

    // RoPE on Q (16 heads) and K (8 heads)
    {
        int tq = SEQ * NH * (HD / 2);
        rope_kernel<<<(tq + 255) / 256, blk>>>(q, cosT, sinT, NH);
        int tk = SEQ * NKV * (HD / 2);
        rope_kernel<<<(tk + 255) / 256, blk>>>(k, cosT, sinT, NKV);
    }

    // scores[h] = Q_h @ K_{h/2}^T  (NT, batched over 16 heads, causal tile skip)
    sgemm<true><<<dim3(16, 16, NH), blk>>>(q, k, sc, SEQ, SEQ, HD,
                                           NH * HD, NKV * HD, SEQ,
                                           HD, HD, (long long)SEQ * SEQ, 2, 1, 0);

    // causal softmax (applies 1/sqrt(D) scaling, zero-fills masked tail)
    softmax_kernel<<<dim3(SEQ, NH), blk>>>(sc);

    // ctx[h] = P_h @ V_{h/2}  (NN, batched, K-loop clamped by causality)
    sgemm<false><<<dim3(1, 16, NH), blk>>>(sc, v, ctx, SEQ, HD, SEQ,
                                           SEQ, NKV * HD, NH * HD,
                                           (long long)SEQ * SEQ, HD, HD, 2, 0, 1);

    // out = ctx @ Wo^T  (NT)
    sgemm<true><<<dim3(16, 16, 1), blk>>>(ctx, Wo, out, SEQ, HID, NH * HD,
                                          NH * HD, NH * HD, HID, 0, 0, 0, 1, 0, 0);
}